// round 12
// baseline (speedup 1.0000x reference)
#include <cuda_runtime.h>
#include <cuda_bf16.h>

// ---------------- problem constants ----------------
#define NB 16
#define NC 32
#define NH 192
#define NW 192
#define NE 8
#define HWSZ (NH*NW)

// conv tile: 8 rows x 64 cols per block, 32 outs
// og = tid>>6 (8 outs each); pt = tid&63: rp = pt>>4 (2 rows), q16 = pt&15
// pixels per thread: 2 rows x 4 cols at (2rp, 2rp+1) x [q16*4 .. q16*4+3]
#define TH 8
#define TW 64
#define THREADS 256
#define GPITCH 68                 // 66 cols padded to 68 (16B-aligned rows)
#define GPLANE (10*GPITCH)        // 680 floats per g-plane
#define NPL 12                    // planes per chunk: 4 x-channels x 3 bases
#define NCHUNKS 8
#define WCH_ULL (NPL*9*32)        // 3456 duplicated weights per chunk
#define RAWF 72                   // raw floats per staged row (18 x 16B)
#define RAWROWS 40                // 4 x-channels x 10 rows
#define RAWBYTES (RAWROWS*RAWF*4) // 11520
// smem: gs + go (dual parity) + weights + raw x buffer
#define SMEM_BYTES (2*NPL*GPLANE*4 + WCH_ULL*8 + RAWBYTES)   // 104448
#define STAGE_N (4*660)           // 2640 transform elements per chunk

typedef unsigned long long ull;

// ---------------- device globals (scratch) ----------------
__device__ float g_gate[NB*NC];
__device__ float g_scale[NB];
__device__ float g_bias[NC*9];
__device__ __align__(16) ull g_wdup[NCHUNKS*WCH_ULL];
__device__ unsigned int g_cnt = 0;

// ---------------- helpers ----------------
__device__ __forceinline__ ull pack2(float lo, float hi) {
    ull r; asm("mov.b64 %0, {%1, %2};" : "=l"(r) : "f"(lo), "f"(hi)); return r;
}
__device__ __forceinline__ void unpack2(ull v, float& lo, float& hi) {
    asm("mov.b64 {%0, %1}, %2;" : "=f"(lo), "=f"(hi) : "l"(v));
}
__device__ __forceinline__ void fma2(ull& d, ull a, ull b) {
    asm("fma.rn.f32x2 %0, %1, %2, %3;" : "=l"(d) : "l"(a), "l"(b), "l"(d));
}
__device__ __forceinline__ float silu_f(float z) {
    float e = __expf(-z);
    return __fdividef(z, 1.0f + e);
}
__device__ __forceinline__ float fast_tanh(float x) {
    float e = __expf(2.0f * x);
    return 1.0f - __fdividef(2.0f, e + 1.0f);
}
__device__ __forceinline__ float cv2_8(const float* v) {
    float m = 0.f;
    for (int i = 0; i < 8; ++i) m += v[i];
    m *= 0.125f;
    float var = 0.f;
    for (int i = 0; i < 8; ++i) { float d = v[i] - m; var += d * d; }
    var *= (1.0f / 7.0f);
    return var / (m * m + 1e-10f);
}
__device__ __forceinline__ unsigned smem_u32(const void* p) {
    return (unsigned)__cvta_generic_to_shared(p);
}
__device__ __forceinline__ void cp_async16(unsigned dst, const void* src) {
    asm volatile("cp.async.cg.shared.global [%0], [%1], 16;\n"
                 :: "r"(dst), "l"(src));
}
__device__ __forceinline__ void cp_commit() {
    asm volatile("cp.async.commit_group;\n");
}
__device__ __forceinline__ void cp_wait0() {
    asm volatile("cp.async.wait_group 0;\n");
}
__device__ __forceinline__ void cp_wait1() {
    asm volatile("cp.async.wait_group 1;\n");
}

// ---------------- kernel 1: mean + (last block) gating ----------------
__global__ void k_gate(const float* __restrict__ x, const float* __restrict__ wg,
                       float* __restrict__ loss_out) {
    int plane = blockIdx.x;                    // 0..511
    const float* p = x + (size_t)plane * HWSZ;
    float s = 0.f;
    for (int i = threadIdx.x; i < HWSZ; i += 256) s += p[i];
    __shared__ float red[256];
    red[threadIdx.x] = s;
    __syncthreads();
    for (int off = 128; off > 0; off >>= 1) {
        if (threadIdx.x < off) red[threadIdx.x] += red[threadIdx.x + off];
        __syncthreads();
    }
    __shared__ bool is_last;
    if (threadIdx.x == 0) {
        g_gate[plane] = red[0] * (1.0f / (float)HWSZ);
        __threadfence();
        unsigned int c = atomicAdd(&g_cnt, 1u);
        is_last = (c == (unsigned)(NB * NC - 1));
    }
    __syncthreads();
    if (!is_last) return;

    __threadfence();
    __shared__ float sgates[NB][NE];
    int n = threadIdx.x;
    if (n < NB) {
        float logit[NE];
        #pragma unroll
        for (int e = 0; e < NE; ++e) logit[e] = 0.f;
        for (int c = 0; c < NC; ++c) {
            float gx = g_gate[n * NC + c];
            #pragma unroll
            for (int e = 0; e < NE; ++e) logit[e] += gx * wg[c * NE + e];
        }
        float mx = logit[0];
        #pragma unroll
        for (int e = 1; e < NE; ++e) mx = fmaxf(mx, logit[e]);
        float pr[NE]; float se = 0.f;
        #pragma unroll
        for (int e = 0; e < NE; ++e) { pr[e] = __expf(logit[e] - mx); se += pr[e]; }
        float inv = 1.0f / se;
        #pragma unroll
        for (int e = 0; e < NE; ++e) pr[e] *= inv;
        int i0 = 0;
        #pragma unroll
        for (int e = 1; e < NE; ++e) if (pr[e] > pr[i0]) i0 = e;
        int i1 = (i0 == 0) ? 1 : 0;
        #pragma unroll
        for (int e = 0; e < NE; ++e) if (e != i0 && pr[e] > pr[i1]) i1 = e;
        float v0 = pr[i0], v1 = pr[i1];
        float denom = v0 + v1 + 1e-6f;
        #pragma unroll
        for (int e = 0; e < NE; ++e) sgates[n][e] = 0.f;
        sgates[n][i0] = v0 / denom;
        sgates[n][i1] = v1 / denom;
        g_scale[n] = (v0 + v1) / denom;
    }
    __syncthreads();
    if (threadIdx.x == 0) {
        float imp[NE], ld[NE];
        #pragma unroll
        for (int e = 0; e < NE; ++e) { imp[e] = 0.f; ld[e] = 0.f; }
        for (int b = 0; b < NB; ++b)
            for (int e = 0; e < NE; ++e) {
                float v = sgates[b][e];
                imp[e] += v;
                if (v > 0.f) ld[e] += 1.f;
            }
        *loss_out = 0.01f * (cv2_8(imp) + cv2_8(ld));
        g_cnt = 0;                 // reset for next replay
    }
}

// ---------------- kernel 2: weight prep (wdup + bias tables) ----------------
__global__ void k_wprep(const float* __restrict__ pw) {
    if (blockIdx.x < 108) {
        int idx = blockIdx.x * 256 + threadIdx.x;       // < 27648
        int o  = idx & 31;
        int k  = (idx >> 5) % 9;
        int t  = (idx >> 5) / 9;                        // cb*12 + plane
        int plane = t % 12;
        int cb = t / 12;
        int c4 = plane / 3;
        int bi = plane % 3;
        int gi = (bi + 1) * 32 + cb * 4 + c4;
        float w = pw[(size_t)o * (128 * 9) + gi * 9 + k];
        g_wdup[idx] = pack2(w, w);
    } else {
        int o = threadIdx.x;
        if (o >= 32) return;
        const float G0 = 0.7310585786300049f;   // silu(1)
        float T[9];
        #pragma unroll
        for (int k = 0; k < 9; ++k) T[k] = 0.f;
        for (int c = 0; c < 32; ++c)
            #pragma unroll
            for (int k = 0; k < 9; ++k) T[k] += pw[(size_t)o * (128 * 9) + c * 9 + k];
        #pragma unroll
        for (int k = 0; k < 9; ++k) T[k] *= G0;
        float S = 0.f;
        #pragma unroll
        for (int k = 0; k < 9; ++k) S += T[k];
        g_bias[o * 9 + 0] = S;
        g_bias[o * 9 + 1] = T[0] + T[1] + T[2];
        g_bias[o * 9 + 2] = T[6] + T[7] + T[8];
        g_bias[o * 9 + 3] = T[0] + T[3] + T[6];
        g_bias[o * 9 + 4] = T[2] + T[5] + T[8];
        g_bias[o * 9 + 5] = T[0];
        g_bias[o * 9 + 6] = T[2];
        g_bias[o * 9 + 7] = T[6];
        g_bias[o * 9 + 8] = T[8];
    }
}

// ---------------- kernel 2.5: no-op spacer (keeps ncu on k_moe_conv) -------
__global__ void k_spacer() { }

// ---------------- kernel 3: fused basis + conv + bias + scale ----------------
__global__ void __launch_bounds__(THREADS, 2)
k_moe_conv(const float* __restrict__ x, const float* __restrict__ betaw,
           float* __restrict__ y) {
    extern __shared__ float smem[];
    float* gs  = smem;                                 // NPL * GPLANE floats
    float* go  = smem + NPL * GPLANE;                  // shifted copy (g[j+1])
    ull*   ws  = (ull*)(smem + 2 * NPL * GPLANE);
    float* raw = (float*)(ws + WCH_ULL);               // RAWROWS*RAWF floats

    const int n  = blockIdx.z;
    const int y0 = blockIdx.y * TH;
    const int x0 = blockIdx.x * TW;
    const int tid = threadIdx.x;
    const int og  = tid >> 6;          // 0..3
    const int pt  = tid & 63;
    const int rp  = pt >> 4;           // 0..3 -> output rows 2rp, 2rp+1
    const int q16 = pt & 15;           // 0..15
    const int col0 = q16 * 4;
    const int og8  = og * 8;

    const float B2 = 2.25f * betaw[1];
    const float B3 = (100.0f / 3.0f) * betaw[2];

    // acc[o*4 + s*2 + h]: out og8+o, row 2rp+s, pixel pair h (c0c1 / c2c3)
    ull acc[32];
    #pragma unroll
    for (int i = 0; i < 32; ++i) acc[i] = 0ull;

    const float* xn = x + (size_t)n * NC * HWSZ;

    // ---- raw-x prefetch for chunk `cb`: 40 rows x 18 aligned 16B chunks ----
    auto prefetch_raw = [&](int cb) {
        const float* xc = xn + (size_t)(cb * 4) * HWSZ;
        for (int j = tid; j < RAWROWS * 18; j += THREADS) {
            int rowid = j / 18;            // c4*10 + r
            int c     = j - rowid * 18;
            int r  = rowid % 10;
            int c4 = rowid / 10;
            int gy = y0 - 1 + r;
            int g0 = x0 - 4 + 4 * c;
            if ((unsigned)gy < (unsigned)NH && (unsigned)g0 <= (unsigned)(NW - 4)) {
                unsigned dst = smem_u32(raw + rowid * RAWF + 4 * c);
                cp_async16(dst, xc + (size_t)c4 * HWSZ + gy * NW + g0);
            }
        }
        cp_commit();
    };
    // ---- weight prefetch for chunk `cb` (cp.async, 1728 x 16B) ----
    auto prefetch_w = [&](int cb) {
        const uint4* src = (const uint4*)(g_wdup + cb * WCH_ULL);
        uint4* dst = (uint4*)ws;
        for (int i = tid; i < WCH_ULL / 2; i += THREADS)
            cp_async16(smem_u32(dst + i), src + i);
        cp_commit();
    };

    // prologue: start raw(0) fetch
    prefetch_raw(0);                    // outstanding: R0

    #pragma unroll 1
    for (int cb = 0; cb < NCHUNKS; ++cb) {
        __syncthreads();                // gs/go/ws free (GEMM(cb-1) done)
        prefetch_w(cb);                 // outstanding: R(cb), W(cb)
        cp_wait1();                     // own R(cb) groups retired
        __syncthreads();                // ALL threads' R(cb) complete -> raw visible

        // ---- transform raw x -> g planes (LDS + MUFU + STS, no gmem) ----
        #pragma unroll
        for (int k = 0; k < 11; ++k) {
            int idx = tid + k * THREADS;
            if (idx >= STAGE_N) break;
            int c4  = idx / 660;
            int rem = idx - c4 * 660;
            int r   = rem / 66;
            int cc  = rem - r * 66;
            int gy = y0 - 1 + r;
            int gx = x0 - 1 + cc;
            float g1, g2, g3;
            if ((unsigned)gy < (unsigned)NH && (unsigned)gx < (unsigned)NW) {
                float xv = raw[(c4 * 10 + r) * RAWF + cc + 3];
                float t  = fast_tanh(xv);
                float P2 = t * t - B2;
                float P3 = t * P2 - B3 * t;
                g1 = silu_f(t);
                g2 = silu_f(P2);
                g3 = silu_f(P3);
            } else {
                g1 = g2 = g3 = 0.f;
            }
            int sb = c4 * 3 * GPLANE + r * GPITCH + cc;
            gs[sb]              = g1;
            gs[sb + GPLANE]     = g2;
            gs[sb + 2 * GPLANE] = g3;
            if (cc >= 1) {                 // shifted copy: go[j] = g[j+1]
                go[sb - 1]              = g1;
                go[sb - 1 + GPLANE]     = g2;
                go[sb - 1 + 2 * GPLANE] = g3;
            }
        }
        cp_wait0();                     // own W(cb) groups retired
        __syncthreads();                // all W(cb) complete + gs/go visible

        // ---- start next chunk's raw fetch under the GEMM ----
        if (cb + 1 < NCHUNKS) prefetch_raw(cb + 1);   // outstanding: R(cb+1)

        // ---- register-tiled f32x2 GEMM: 12 planes x 9 taps ----
        // act window (4 consecutive gs rows) loaded ONCE per plane, reused
        // across all 3 ky taps for 2 output rows.
        const ull*   wp = ws + og8;
        const int    base0 = (2 * rp) * GPITCH + col0;
        const float* gsb = gs + base0;
        const float* gob = go + base0;
        #pragma unroll 1
        for (int ch = 0; ch < NPL; ++ch) {
            ulonglong2 E[4]; ull P[4]; ulonglong2 O[4];
            #pragma unroll
            for (int r = 0; r < 4; ++r) {
                E[r] = *(const ulonglong2*)(gsb + r * GPITCH);       // pa0, pa2
                P[r] = *(const ull*)(gsb + r * GPITCH + 4);          // pa4
                O[r] = *(const ulonglong2*)(gob + r * GPITCH);       // pa1, pa3
            }
            #pragma unroll
            for (int t = 0; t < 3; ++t) {
                #pragma unroll
                for (int kx = 0; kx < 3; ++kx) {
                    const ull* w = wp + (t * 3 + kx) * 32;
                    ulonglong2 w01 = *(const ulonglong2*)(w + 0);
                    ulonglong2 w23 = *(const ulonglong2*)(w + 2);
                    ulonglong2 w45 = *(const ulonglong2*)(w + 4);
                    ulonglong2 w67 = *(const ulonglong2*)(w + 6);
                    #pragma unroll
                    for (int s = 0; s < 2; ++s) {
                        const int ar = t + s;
                        ull gA = (kx == 0) ? E[ar].x : (kx == 1) ? O[ar].x : E[ar].y;
                        ull gB = (kx == 0) ? E[ar].y : (kx == 1) ? O[ar].y : P[ar];
                        const int b = s * 2;
                        fma2(acc[0  + b], w01.x, gA); fma2(acc[1  + b], w01.x, gB);
                        fma2(acc[4  + b], w01.y, gA); fma2(acc[5  + b], w01.y, gB);
                        fma2(acc[8  + b], w23.x, gA); fma2(acc[9  + b], w23.x, gB);
                        fma2(acc[12 + b], w23.y, gA); fma2(acc[13 + b], w23.y, gB);
                        fma2(acc[16 + b], w45.x, gA); fma2(acc[17 + b], w45.x, gB);
                        fma2(acc[20 + b], w45.y, gA); fma2(acc[21 + b], w45.y, gB);
                        fma2(acc[24 + b], w67.x, gA); fma2(acc[25 + b], w67.x, gB);
                        fma2(acc[28 + b], w67.y, gA); fma2(acc[29 + b], w67.y, gB);
                    }
                }
            }
            wp  += 9 * 32;
            gsb += GPLANE;
            gob += GPLANE;
        }
    }

    // ---- epilogue: P0 bias + per-batch gate scale + store ----
    float s = g_scale[n];
    int gx0 = x0 + col0;
    bool left  = (gx0 == 0);
    bool right = (gx0 + 3 == NW - 1);
    #pragma unroll
    for (int o = 0; o < 8; ++o) {
        const float* bt = g_bias + (og8 + o) * 9;
        float S  = bt[0];
        #pragma unroll
        for (int sr = 0; sr < 2; ++sr) {
            int gy = y0 + 2 * rp + sr;
            bool top = (gy == 0), bot = (gy == NH - 1);
            float bbase = S - (top ? bt[1] : 0.f) - (bot ? bt[2] : 0.f);
            float bl = bbase, br = bbase;
            if (left)
                bl += -bt[3] + (top ? bt[5] : 0.f) + (bot ? bt[7] : 0.f);
            if (right)
                br += -bt[4] + (top ? bt[6] : 0.f) + (bot ? bt[8] : 0.f);
            float v0, v1, v2, v3;
            unpack2(acc[o * 4 + sr * 2],     v0, v1);
            unpack2(acc[o * 4 + sr * 2 + 1], v2, v3);
            float4 out;
            out.x = (v0 + bl)    * s;
            out.y = (v1 + bbase) * s;
            out.z = (v2 + bbase) * s;
            out.w = (v3 + br)    * s;
            size_t off = ((size_t)(n * NC + og8 + o) * NH + gy) * NW + gx0;
            *(float4*)(y + off) = out;
        }
    }
}

// ---------------- launcher ----------------
extern "C" void kernel_launch(void* const* d_in, const int* in_sizes, int n_in,
                              void* d_out, int out_size) {
    const float* x  = (const float*)d_in[0];
    const float* wg = (const float*)d_in[1];
    const float* pw = (const float*)d_in[2];
    const float* bw = (const float*)d_in[3];
    float* out = (float*)d_out;

    cudaFuncSetAttribute(k_moe_conv, cudaFuncAttributeMaxDynamicSharedMemorySize, SMEM_BYTES);

    k_gate<<<NB * NC, 256>>>(x, wg, out + (out_size - 1));    // launch 0
    k_wprep<<<109, 256>>>(pw);                                 // launch 1
    k_spacer<<<1, 32>>>();                                     // launch 2 (aligns ncu)
    dim3 grid(NW / TW, NH / TH, NB);
    k_moe_conv<<<grid, THREADS, SMEM_BYTES>>>(x, bw, out);     // launch 3 <- profiled
}

// round 13
// speedup vs baseline: 1.1014x; 1.1014x over previous
#include <cuda_runtime.h>
#include <cuda_bf16.h>

// ---------------- problem constants ----------------
#define NB 16
#define NC 32
#define NH 192
#define NW 192
#define NE 8
#define HWSZ (NH*NW)

// conv tile: 8 rows x 64 cols per block, 32 outs
#define TH 8
#define TW 64
#define THREADS 256
#define GPITCH 68                 // 66 cols padded to 68 (16B-aligned rows)
#define GPLANE (10*GPITCH)        // 680 floats per g-plane
#define NPL 12                    // planes per chunk: 4 x-channels x 3 bases
#define NCHUNKS 8
#define WCH_ULL (NPL*9*32)        // 3456 duplicated weights per chunk
#define RAWF 72                   // raw floats per staged row (18 x 16B)
#define RAWROWS 40                // 4 x-channels x 10 rows
#define RAWBYTES (RAWROWS*RAWF*4) // 11520
// smem: gs + go (dual parity) + weights + raw x buffer
#define SMEM_BYTES (2*NPL*GPLANE*4 + WCH_ULL*8 + RAWBYTES)   // 104448
#define STAGE_N (4*660)           // 2640 transform elements per chunk

typedef unsigned long long ull;

// ---------------- device globals (scratch) ----------------
__device__ float g_gate[NB*NC];
__device__ float g_scale[NB];
__device__ float g_bias[NC*9];
__device__ __align__(16) ull g_wdup[NCHUNKS*WCH_ULL];
__device__ unsigned int g_cnt = 0;

// ---------------- helpers ----------------
__device__ __forceinline__ ull pack2(float lo, float hi) {
    ull r; asm("mov.b64 %0, {%1, %2};" : "=l"(r) : "f"(lo), "f"(hi)); return r;
}
__device__ __forceinline__ void unpack2(ull v, float& lo, float& hi) {
    asm("mov.b64 {%0, %1}, %2;" : "=f"(lo), "=f"(hi) : "l"(v));
}
__device__ __forceinline__ void fma2(ull& d, ull a, ull b) {
    asm("fma.rn.f32x2 %0, %1, %2, %3;" : "=l"(d) : "l"(a), "l"(b), "l"(d));
}
__device__ __forceinline__ float silu_f(float z) {
    float e = __expf(-z);
    return __fdividef(z, 1.0f + e);
}
__device__ __forceinline__ float fast_tanh(float x) {
    float e = __expf(2.0f * x);
    return 1.0f - __fdividef(2.0f, e + 1.0f);
}
__device__ __forceinline__ float cv2_8(const float* v) {
    float m = 0.f;
    for (int i = 0; i < 8; ++i) m += v[i];
    m *= 0.125f;
    float var = 0.f;
    for (int i = 0; i < 8; ++i) { float d = v[i] - m; var += d * d; }
    var *= (1.0f / 7.0f);
    return var / (m * m + 1e-10f);
}
__device__ __forceinline__ unsigned smem_u32(const void* p) {
    return (unsigned)__cvta_generic_to_shared(p);
}
__device__ __forceinline__ void cp_async16(unsigned dst, const void* src) {
    asm volatile("cp.async.cg.shared.global [%0], [%1], 16;\n"
                 :: "r"(dst), "l"(src));
}
__device__ __forceinline__ void cp_commit() {
    asm volatile("cp.async.commit_group;\n");
}
__device__ __forceinline__ void cp_wait0() {
    asm volatile("cp.async.wait_group 0;\n");
}
__device__ __forceinline__ void cp_wait1() {
    asm volatile("cp.async.wait_group 1;\n");
}

// ---------------- kernel 1: mean (float4, MLP=4) + (last block) gating -----
__global__ void k_gate(const float* __restrict__ x, const float* __restrict__ wg,
                       float* __restrict__ loss_out) {
    int plane = blockIdx.x;                    // 0..511
    const float4* p = (const float4*)(x + (size_t)plane * HWSZ);
    // 9216 float4 per plane; 256 threads -> 36 iters; 4 partial sums for MLP
    float s0 = 0.f, s1 = 0.f, s2 = 0.f, s3 = 0.f;
    #pragma unroll 4
    for (int i = threadIdx.x; i < HWSZ / 4; i += 256) {
        float4 v = p[i];
        s0 += v.x; s1 += v.y; s2 += v.z; s3 += v.w;
    }
    float s = (s0 + s1) + (s2 + s3);
    __shared__ float red[256];
    red[threadIdx.x] = s;
    __syncthreads();
    for (int off = 128; off > 0; off >>= 1) {
        if (threadIdx.x < off) red[threadIdx.x] += red[threadIdx.x + off];
        __syncthreads();
    }
    __shared__ bool is_last;
    if (threadIdx.x == 0) {
        g_gate[plane] = red[0] * (1.0f / (float)HWSZ);
        __threadfence();
        unsigned int c = atomicAdd(&g_cnt, 1u);
        is_last = (c == (unsigned)(NB * NC - 1));
    }
    __syncthreads();
    if (!is_last) return;

    __threadfence();
    __shared__ float sgates[NB][NE];
    int n = threadIdx.x;
    if (n < NB) {
        float logit[NE];
        #pragma unroll
        for (int e = 0; e < NE; ++e) logit[e] = 0.f;
        for (int c = 0; c < NC; ++c) {
            float gx = g_gate[n * NC + c];
            #pragma unroll
            for (int e = 0; e < NE; ++e) logit[e] += gx * wg[c * NE + e];
        }
        float mx = logit[0];
        #pragma unroll
        for (int e = 1; e < NE; ++e) mx = fmaxf(mx, logit[e]);
        float pr[NE]; float se = 0.f;
        #pragma unroll
        for (int e = 0; e < NE; ++e) { pr[e] = __expf(logit[e] - mx); se += pr[e]; }
        float inv = 1.0f / se;
        #pragma unroll
        for (int e = 0; e < NE; ++e) pr[e] *= inv;
        int i0 = 0;
        #pragma unroll
        for (int e = 1; e < NE; ++e) if (pr[e] > pr[i0]) i0 = e;
        int i1 = (i0 == 0) ? 1 : 0;
        #pragma unroll
        for (int e = 0; e < NE; ++e) if (e != i0 && pr[e] > pr[i1]) i1 = e;
        float v0 = pr[i0], v1 = pr[i1];
        float denom = v0 + v1 + 1e-6f;
        #pragma unroll
        for (int e = 0; e < NE; ++e) sgates[n][e] = 0.f;
        sgates[n][i0] = v0 / denom;
        sgates[n][i1] = v1 / denom;
        g_scale[n] = (v0 + v1) / denom;
    }
    __syncthreads();
    if (threadIdx.x == 0) {
        float imp[NE], ld[NE];
        #pragma unroll
        for (int e = 0; e < NE; ++e) { imp[e] = 0.f; ld[e] = 0.f; }
        for (int b = 0; b < NB; ++b)
            for (int e = 0; e < NE; ++e) {
                float v = sgates[b][e];
                imp[e] += v;
                if (v > 0.f) ld[e] += 1.f;
            }
        *loss_out = 0.01f * (cv2_8(imp) + cv2_8(ld));
        g_cnt = 0;                 // reset for next replay
    }
}

// ---------------- kernel 2: weight prep (wdup + bias tables) ----------------
__global__ void k_wprep(const float* __restrict__ pw) {
    if (blockIdx.x < 108) {
        int idx = blockIdx.x * 256 + threadIdx.x;       // < 27648
        int o  = idx & 31;
        int k  = (idx >> 5) % 9;
        int t  = (idx >> 5) / 9;                        // cb*12 + plane
        int plane = t % 12;
        int cb = t / 12;
        int c4 = plane / 3;
        int bi = plane % 3;
        int gi = (bi + 1) * 32 + cb * 4 + c4;
        float w = pw[(size_t)o * (128 * 9) + gi * 9 + k];
        g_wdup[idx] = pack2(w, w);
    } else {
        int o = threadIdx.x;
        if (o >= 32) return;
        const float G0 = 0.7310585786300049f;   // silu(1)
        float T[9];
        #pragma unroll
        for (int k = 0; k < 9; ++k) T[k] = 0.f;
        for (int c = 0; c < 32; ++c)
            #pragma unroll
            for (int k = 0; k < 9; ++k) T[k] += pw[(size_t)o * (128 * 9) + c * 9 + k];
        #pragma unroll
        for (int k = 0; k < 9; ++k) T[k] *= G0;
        float S = 0.f;
        #pragma unroll
        for (int k = 0; k < 9; ++k) S += T[k];
        g_bias[o * 9 + 0] = S;
        g_bias[o * 9 + 1] = T[0] + T[1] + T[2];
        g_bias[o * 9 + 2] = T[6] + T[7] + T[8];
        g_bias[o * 9 + 3] = T[0] + T[3] + T[6];
        g_bias[o * 9 + 4] = T[2] + T[5] + T[8];
        g_bias[o * 9 + 5] = T[0];
        g_bias[o * 9 + 6] = T[2];
        g_bias[o * 9 + 7] = T[6];
        g_bias[o * 9 + 8] = T[8];
    }
}

// ---------------- kernel 2.5: no-op spacer (keeps ncu on k_moe_conv) -------
__global__ void k_spacer() { }

// ---------------- kernel 3: fused basis + conv + bias + scale ----------------
__global__ void __launch_bounds__(THREADS, 2)
k_moe_conv(const float* __restrict__ x, const float* __restrict__ betaw,
           float* __restrict__ y) {
    extern __shared__ float smem[];
    float* gs  = smem;                                 // NPL * GPLANE floats
    float* go  = smem + NPL * GPLANE;                  // shifted copy (g[j+1])
    ull*   ws  = (ull*)(smem + 2 * NPL * GPLANE);
    float* raw = (float*)(ws + WCH_ULL);               // RAWROWS*RAWF floats

    const int n  = blockIdx.z;
    const int y0 = blockIdx.y * TH;
    const int x0 = blockIdx.x * TW;
    const int tid = threadIdx.x;
    const int og  = tid >> 6;          // 0..3
    const int pt  = tid & 63;
    const int row = pt >> 3;           // 0..7
    const int q   = pt & 7;            // 0..7
    const int col0 = q * 4;
    const int og8  = og * 8;

    const float B2 = 2.25f * betaw[1];
    const float B3 = (100.0f / 3.0f) * betaw[2];

    ull acc[32];
    #pragma unroll
    for (int i = 0; i < 32; ++i) acc[i] = 0ull;

    const float* xn = x + (size_t)n * NC * HWSZ;

    // ---- raw-x prefetch for chunk `cb`: 40 rows x 18 aligned 16B chunks ----
    auto prefetch_raw = [&](int cb) {
        const float* xc = xn + (size_t)(cb * 4) * HWSZ;
        for (int j = tid; j < RAWROWS * 18; j += THREADS) {
            int rowid = j / 18;            // c4*10 + r
            int c     = j - rowid * 18;
            int r  = rowid % 10;
            int c4 = rowid / 10;
            int gy = y0 - 1 + r;
            int g0 = x0 - 4 + 4 * c;
            if ((unsigned)gy < (unsigned)NH && (unsigned)g0 <= (unsigned)(NW - 4)) {
                unsigned dst = smem_u32(raw + rowid * RAWF + 4 * c);
                cp_async16(dst, xc + (size_t)c4 * HWSZ + gy * NW + g0);
            }
        }
        cp_commit();
    };
    // ---- weight prefetch for chunk `cb` (cp.async, 1728 x 16B) ----
    auto prefetch_w = [&](int cb) {
        const uint4* src = (const uint4*)(g_wdup + cb * WCH_ULL);
        uint4* dst = (uint4*)ws;
        for (int i = tid; i < WCH_ULL / 2; i += THREADS)
            cp_async16(smem_u32(dst + i), src + i);
        cp_commit();
    };

    // prologue: start raw(0) fetch
    prefetch_raw(0);                    // outstanding: R0

    #pragma unroll 1
    for (int cb = 0; cb < NCHUNKS; ++cb) {
        __syncthreads();                // gs/go/ws free (GEMM(cb-1) done)
        prefetch_w(cb);                 // outstanding: R(cb), W(cb)
        cp_wait1();                     // own R(cb) groups retired
        __syncthreads();                // ALL threads' R(cb) complete -> raw visible

        // ---- transform raw x -> g planes (LDS + MUFU + STS, no gmem) ----
        #pragma unroll
        for (int k = 0; k < 11; ++k) {
            int idx = tid + k * THREADS;
            if (idx >= STAGE_N) break;
            int c4  = idx / 660;
            int rem = idx - c4 * 660;
            int r   = rem / 66;
            int cc  = rem - r * 66;
            int gy = y0 - 1 + r;
            int gx = x0 - 1 + cc;
            float g1, g2, g3;
            if ((unsigned)gy < (unsigned)NH && (unsigned)gx < (unsigned)NW) {
                float xv = raw[(c4 * 10 + r) * RAWF + cc + 3];
                float t  = fast_tanh(xv);
                float P2 = t * t - B2;
                float P3 = t * P2 - B3 * t;
                g1 = silu_f(t);
                g2 = silu_f(P2);
                g3 = silu_f(P3);
            } else {
                g1 = g2 = g3 = 0.f;
            }
            int sb = c4 * 3 * GPLANE + r * GPITCH + cc;
            gs[sb]              = g1;
            gs[sb + GPLANE]     = g2;
            gs[sb + 2 * GPLANE] = g3;
            if (cc >= 1) {                 // shifted copy: go[j] = g[j+1]
                go[sb - 1]              = g1;
                go[sb - 1 + GPLANE]     = g2;
                go[sb - 1 + 2 * GPLANE] = g3;
            }
        }
        cp_wait0();                     // own W(cb) groups retired
        __syncthreads();                // all W(cb) complete + gs/go visible

        // ---- start next chunk's raw fetch under the GEMM ----
        if (cb + 1 < NCHUNKS) prefetch_raw(cb + 1);   // outstanding: R(cb+1)

        // ---- register-tiled f32x2 GEMM: 12 planes x 9 taps, zero packs ----
        const ull*   wp = ws + og8;
        const int    base0 = row * GPITCH + col0;
        const float* gsb = gs + base0;
        const float* gob = go + base0;
        #pragma unroll 2
        for (int ch = 0; ch < NPL; ++ch) {
            #pragma unroll
            for (int ky = 0; ky < 3; ++ky) {
                const int ro = ky * GPITCH;
                ulonglong2 ea = *(const ulonglong2*)(gsb + ro);        // pa0, pa2
                ull        pa4 = *(const ull*)(gsb + ro + 4);
                ulonglong2 oa = *(const ulonglong2*)(gob + ro);        // pa1, pa3
                ulonglong2 eb = *(const ulonglong2*)(gsb + ro + 32);   // pb0, pb2
                ull        pb4 = *(const ull*)(gsb + ro + 36);
                ulonglong2 ob = *(const ulonglong2*)(gob + ro + 32);   // pb1, pb3
                #pragma unroll
                for (int kx = 0; kx < 3; ++kx) {
                    ull gA = (kx == 0) ? ea.x : (kx == 1) ? oa.x : ea.y;
                    ull gB = (kx == 0) ? ea.y : (kx == 1) ? oa.y : pa4;
                    ull gC = (kx == 0) ? eb.x : (kx == 1) ? ob.x : eb.y;
                    ull gD = (kx == 0) ? eb.y : (kx == 1) ? ob.y : pb4;
                    const ull* w = wp + (ky * 3 + kx) * 32;
                    ulonglong2 w01 = *(const ulonglong2*)(w + 0);
                    ulonglong2 w23 = *(const ulonglong2*)(w + 2);
                    ulonglong2 w45 = *(const ulonglong2*)(w + 4);
                    ulonglong2 w67 = *(const ulonglong2*)(w + 6);
                    fma2(acc[0],  w01.x, gA); fma2(acc[1],  w01.x, gB);
                    fma2(acc[2],  w01.x, gC); fma2(acc[3],  w01.x, gD);
                    fma2(acc[4],  w01.y, gA); fma2(acc[5],  w01.y, gB);
                    fma2(acc[6],  w01.y, gC); fma2(acc[7],  w01.y, gD);
                    fma2(acc[8],  w23.x, gA); fma2(acc[9],  w23.x, gB);
                    fma2(acc[10], w23.x, gC); fma2(acc[11], w23.x, gD);
                    fma2(acc[12], w23.y, gA); fma2(acc[13], w23.y, gB);
                    fma2(acc[14], w23.y, gC); fma2(acc[15], w23.y, gD);
                    fma2(acc[16], w45.x, gA); fma2(acc[17], w45.x, gB);
                    fma2(acc[18], w45.x, gC); fma2(acc[19], w45.x, gD);
                    fma2(acc[20], w45.y, gA); fma2(acc[21], w45.y, gB);
                    fma2(acc[22], w45.y, gC); fma2(acc[23], w45.y, gD);
                    fma2(acc[24], w67.x, gA); fma2(acc[25], w67.x, gB);
                    fma2(acc[26], w67.x, gC); fma2(acc[27], w67.x, gD);
                    fma2(acc[28], w67.y, gA); fma2(acc[29], w67.y, gB);
                    fma2(acc[30], w67.y, gC); fma2(acc[31], w67.y, gD);
                }
            }
            wp  += 9 * 32;
            gsb += GPLANE;
            gob += GPLANE;
        }
    }

    // ---- epilogue: P0 bias + per-batch gate scale + store ----
    float s = g_scale[n];
    int gy = y0 + row;
    bool top = (gy == 0), bot = (gy == NH - 1);
    #pragma unroll
    for (int o = 0; o < 8; ++o) {
        const float* bt = g_bias + (og8 + o) * 9;
        float S  = bt[0];
        float bbase = S - (top ? bt[1] : 0.f) - (bot ? bt[2] : 0.f);
        float C0 = bt[3], C2 = bt[4];
        float T00 = bt[5], T02 = bt[6], T20 = bt[7], T22 = bt[8];
        #pragma unroll
        for (int h = 0; h < 2; ++h) {
            int gx0 = x0 + col0 + h * 32;
            float bl = bbase, br = bbase;
            if (gx0 == 0)
                bl += -C0 + (top ? T00 : 0.f) + (bot ? T20 : 0.f);
            if (gx0 + 3 == NW - 1)
                br += -C2 + (top ? T02 : 0.f) + (bot ? T22 : 0.f);
            float v0, v1, v2, v3;
            unpack2(acc[o * 4 + 2 * h],     v0, v1);
            unpack2(acc[o * 4 + 2 * h + 1], v2, v3);
            float4 out;
            out.x = (v0 + bl)    * s;
            out.y = (v1 + bbase) * s;
            out.z = (v2 + bbase) * s;
            out.w = (v3 + br)    * s;
            size_t off = ((size_t)(n * NC + og8 + o) * NH + gy) * NW + gx0;
            *(float4*)(y + off) = out;
        }
    }
}

// ---------------- launcher ----------------
extern "C" void kernel_launch(void* const* d_in, const int* in_sizes, int n_in,
                              void* d_out, int out_size) {
    const float* x  = (const float*)d_in[0];
    const float* wg = (const float*)d_in[1];
    const float* pw = (const float*)d_in[2];
    const float* bw = (const float*)d_in[3];
    float* out = (float*)d_out;

    cudaFuncSetAttribute(k_moe_conv, cudaFuncAttributeMaxDynamicSharedMemorySize, SMEM_BYTES);

    k_gate<<<NB * NC, 256>>>(x, wg, out + (out_size - 1));    // launch 0
    k_wprep<<<109, 256>>>(pw);                                 // launch 1
    k_spacer<<<1, 32>>>();                                     // launch 2 (aligns ncu)
    dim3 grid(NW / TW, NH / TH, NB);
    k_moe_conv<<<grid, THREADS, SMEM_BYTES>>>(x, bw, out);     // launch 3 <- profiled
}

// round 14
// speedup vs baseline: 1.1597x; 1.0529x over previous
#include <cuda_runtime.h>
#include <cuda_bf16.h>

// ---------------- problem constants ----------------
#define NB 16
#define NC 32
#define NH 192
#define NW 192
#define NE 8
#define HWSZ (NH*NW)

// conv tile: 8 rows x 64 cols per block, 32 outs
// og = tid>>6 (8 outs = 4 out-pairs); pt = tid&63: row = pt>>3, q = pt&7
// pixels per thread: 8 = two 4-wide halves at col0=q*4 and col0+32
// f32x2 pairing: (out o, out o+1) per pixel; activations duplicated (g,g)
#define TH 8
#define TW 64
#define THREADS 256
#define GPL 660                   // ull per gd plane: 10 rows x 66 (pitch 66)
#define NPL 12                    // planes per chunk: 4 x-channels x 3 bases
#define NCHUNKS 8
#define WCH_ULL (NPL*9*16)        // 1728 out-pair weights per chunk
#define RAWF 72                   // raw floats per staged row (18 x 16B)
#define RAWROWS 40                // 4 x-channels x 10 rows
#define RAWBYTES (RAWROWS*RAWF*4) // 11520
// smem: gd (dup activations, ull) + weights (out-pair ull) + raw x buffer
#define SMEM_BYTES ((NPL*GPL + WCH_ULL)*8 + RAWBYTES)   // 88704
#define STAGE_N (4*660)           // 2640 transform elements per chunk

typedef unsigned long long ull;

// ---------------- device globals (scratch) ----------------
__device__ float g_gate[NB*NC];
__device__ float g_scale[NB];
__device__ float g_bias[NC*9];
__device__ __align__(16) ull g_wdup[NCHUNKS*WCH_ULL];   // 13824 ull
__device__ unsigned int g_cnt = 0;

// ---------------- helpers ----------------
__device__ __forceinline__ ull pack2(float lo, float hi) {
    ull r; asm("mov.b64 %0, {%1, %2};" : "=l"(r) : "f"(lo), "f"(hi)); return r;
}
__device__ __forceinline__ void unpack2(ull v, float& lo, float& hi) {
    asm("mov.b64 {%0, %1}, %2;" : "=f"(lo), "=f"(hi) : "l"(v));
}
__device__ __forceinline__ void fma2(ull& d, ull a, ull b) {
    asm("fma.rn.f32x2 %0, %1, %2, %3;" : "=l"(d) : "l"(a), "l"(b), "l"(d));
}
__device__ __forceinline__ float silu_f(float z) {
    float e = __expf(-z);
    return __fdividef(z, 1.0f + e);
}
__device__ __forceinline__ float fast_tanh(float x) {
    float e = __expf(2.0f * x);
    return 1.0f - __fdividef(2.0f, e + 1.0f);
}
__device__ __forceinline__ float cv2_8(const float* v) {
    float m = 0.f;
    for (int i = 0; i < 8; ++i) m += v[i];
    m *= 0.125f;
    float var = 0.f;
    for (int i = 0; i < 8; ++i) { float d = v[i] - m; var += d * d; }
    var *= (1.0f / 7.0f);
    return var / (m * m + 1e-10f);
}
__device__ __forceinline__ unsigned smem_u32(const void* p) {
    return (unsigned)__cvta_generic_to_shared(p);
}
__device__ __forceinline__ void cp_async16(unsigned dst, const void* src) {
    asm volatile("cp.async.cg.shared.global [%0], [%1], 16;\n"
                 :: "r"(dst), "l"(src));
}
__device__ __forceinline__ void cp_commit() {
    asm volatile("cp.async.commit_group;\n");
}
__device__ __forceinline__ void cp_wait0() {
    asm volatile("cp.async.wait_group 0;\n");
}
__device__ __forceinline__ void cp_wait1() {
    asm volatile("cp.async.wait_group 1;\n");
}

// ---------------- kernel 1: mean (float4, MLP=4) + (last block) gating -----
__global__ void k_gate(const float* __restrict__ x, const float* __restrict__ wg,
                       float* __restrict__ loss_out) {
    int plane = blockIdx.x;                    // 0..511
    const float4* p = (const float4*)(x + (size_t)plane * HWSZ);
    float s0 = 0.f, s1 = 0.f, s2 = 0.f, s3 = 0.f;
    #pragma unroll 4
    for (int i = threadIdx.x; i < HWSZ / 4; i += 256) {
        float4 v = p[i];
        s0 += v.x; s1 += v.y; s2 += v.z; s3 += v.w;
    }
    float s = (s0 + s1) + (s2 + s3);
    __shared__ float red[256];
    red[threadIdx.x] = s;
    __syncthreads();
    for (int off = 128; off > 0; off >>= 1) {
        if (threadIdx.x < off) red[threadIdx.x] += red[threadIdx.x + off];
        __syncthreads();
    }
    __shared__ bool is_last;
    if (threadIdx.x == 0) {
        g_gate[plane] = red[0] * (1.0f / (float)HWSZ);
        __threadfence();
        unsigned int c = atomicAdd(&g_cnt, 1u);
        is_last = (c == (unsigned)(NB * NC - 1));
    }
    __syncthreads();
    if (!is_last) return;

    __threadfence();
    __shared__ float sgates[NB][NE];
    int n = threadIdx.x;
    if (n < NB) {
        float logit[NE];
        #pragma unroll
        for (int e = 0; e < NE; ++e) logit[e] = 0.f;
        for (int c = 0; c < NC; ++c) {
            float gx = g_gate[n * NC + c];
            #pragma unroll
            for (int e = 0; e < NE; ++e) logit[e] += gx * wg[c * NE + e];
        }
        float mx = logit[0];
        #pragma unroll
        for (int e = 1; e < NE; ++e) mx = fmaxf(mx, logit[e]);
        float pr[NE]; float se = 0.f;
        #pragma unroll
        for (int e = 0; e < NE; ++e) { pr[e] = __expf(logit[e] - mx); se += pr[e]; }
        float inv = 1.0f / se;
        #pragma unroll
        for (int e = 0; e < NE; ++e) pr[e] *= inv;
        int i0 = 0;
        #pragma unroll
        for (int e = 1; e < NE; ++e) if (pr[e] > pr[i0]) i0 = e;
        int i1 = (i0 == 0) ? 1 : 0;
        #pragma unroll
        for (int e = 0; e < NE; ++e) if (e != i0 && pr[e] > pr[i1]) i1 = e;
        float v0 = pr[i0], v1 = pr[i1];
        float denom = v0 + v1 + 1e-6f;
        #pragma unroll
        for (int e = 0; e < NE; ++e) sgates[n][e] = 0.f;
        sgates[n][i0] = v0 / denom;
        sgates[n][i1] = v1 / denom;
        g_scale[n] = (v0 + v1) / denom;
    }
    __syncthreads();
    if (threadIdx.x == 0) {
        float imp[NE], ld[NE];
        #pragma unroll
        for (int e = 0; e < NE; ++e) { imp[e] = 0.f; ld[e] = 0.f; }
        for (int b = 0; b < NB; ++b)
            for (int e = 0; e < NE; ++e) {
                float v = sgates[b][e];
                imp[e] += v;
                if (v > 0.f) ld[e] += 1.f;
            }
        *loss_out = 0.01f * (cv2_8(imp) + cv2_8(ld));
        g_cnt = 0;                 // reset for next replay
    }
}

// ---------------- kernel 2: weight prep (out-pair wdup + bias tables) ------
// g_wdup layout: [cb][plane][tap][op], op=0..15 -> outs (2op, 2op+1)
__global__ void k_wprep(const float* __restrict__ pw) {
    if (blockIdx.x < 54) {
        int idx = blockIdx.x * 256 + threadIdx.x;       // < 13824
        int op  = idx & 15;
        int tap = (idx >> 4) % 9;
        int t   = (idx >> 4) / 9;                       // cb*12 + plane
        int plane = t % 12;
        int cb = t / 12;
        int c4 = plane / 3;
        int bi = plane % 3;
        int gi = (bi + 1) * 32 + cb * 4 + c4;
        float w0 = pw[(size_t)(2 * op)     * (128 * 9) + gi * 9 + tap];
        float w1 = pw[(size_t)(2 * op + 1) * (128 * 9) + gi * 9 + tap];
        g_wdup[idx] = pack2(w0, w1);
    } else {
        int o = threadIdx.x;
        if (o >= 32) return;
        const float G0 = 0.7310585786300049f;   // silu(1)
        float T[9];
        #pragma unroll
        for (int k = 0; k < 9; ++k) T[k] = 0.f;
        for (int c = 0; c < 32; ++c)
            #pragma unroll
            for (int k = 0; k < 9; ++k) T[k] += pw[(size_t)o * (128 * 9) + c * 9 + k];
        #pragma unroll
        for (int k = 0; k < 9; ++k) T[k] *= G0;
        float S = 0.f;
        #pragma unroll
        for (int k = 0; k < 9; ++k) S += T[k];
        g_bias[o * 9 + 0] = S;
        g_bias[o * 9 + 1] = T[0] + T[1] + T[2];
        g_bias[o * 9 + 2] = T[6] + T[7] + T[8];
        g_bias[o * 9 + 3] = T[0] + T[3] + T[6];
        g_bias[o * 9 + 4] = T[2] + T[5] + T[8];
        g_bias[o * 9 + 5] = T[0];
        g_bias[o * 9 + 6] = T[2];
        g_bias[o * 9 + 7] = T[6];
        g_bias[o * 9 + 8] = T[8];
    }
}

// ---------------- kernel 2.5: no-op spacer (keeps ncu on k_moe_conv) -------
__global__ void k_spacer() { }

// ---------------- kernel 3: fused basis + conv + bias + scale ----------------
__global__ void __launch_bounds__(THREADS, 2)
k_moe_conv(const float* __restrict__ x, const float* __restrict__ betaw,
           float* __restrict__ y) {
    extern __shared__ ull smem_u[];
    ull*   gd  = smem_u;                               // NPL * GPL ull (dup acts)
    ull*   ws  = smem_u + NPL * GPL;                   // WCH_ULL out-pair weights
    float* raw = (float*)(ws + WCH_ULL);               // RAWROWS*RAWF floats

    const int n  = blockIdx.z;
    const int y0 = blockIdx.y * TH;
    const int x0 = blockIdx.x * TW;
    const int tid = threadIdx.x;
    const int og  = tid >> 6;          // 0..3
    const int pt  = tid & 63;
    const int row = pt >> 3;           // 0..7
    const int q   = pt & 7;            // 0..7
    const int col0 = q * 4;
    const int og8  = og * 8;

    const float B2 = 2.25f * betaw[1];
    const float B3 = (100.0f / 3.0f) * betaw[2];

    // acc[p*8 + h*4 + j]: out-pair p (outs og8+2p, og8+2p+1),
    // half h (cols col0 / col0+32), pixel j (0..3)
    ull acc[32];
    #pragma unroll
    for (int i = 0; i < 32; ++i) acc[i] = 0ull;

    const float* xn = x + (size_t)n * NC * HWSZ;

    // ---- raw-x prefetch for chunk `cb`: 40 rows x 18 aligned 16B chunks ----
    auto prefetch_raw = [&](int cb) {
        const float* xc = xn + (size_t)(cb * 4) * HWSZ;
        for (int j = tid; j < RAWROWS * 18; j += THREADS) {
            int rowid = j / 18;            // c4*10 + r
            int c     = j - rowid * 18;
            int r  = rowid % 10;
            int c4 = rowid / 10;
            int gy = y0 - 1 + r;
            int g0 = x0 - 4 + 4 * c;
            if ((unsigned)gy < (unsigned)NH && (unsigned)g0 <= (unsigned)(NW - 4)) {
                unsigned dst = smem_u32(raw + rowid * RAWF + 4 * c);
                cp_async16(dst, xc + (size_t)c4 * HWSZ + gy * NW + g0);
            }
        }
        cp_commit();
    };
    // ---- weight prefetch for chunk `cb` (cp.async, 864 x 16B) ----
    auto prefetch_w = [&](int cb) {
        const uint4* src = (const uint4*)(g_wdup + cb * WCH_ULL);
        uint4* dst = (uint4*)ws;
        for (int i = tid; i < WCH_ULL / 2; i += THREADS)
            cp_async16(smem_u32(dst + i), src + i);
        cp_commit();
    };

    // prologue: start raw(0) fetch
    prefetch_raw(0);                    // outstanding: R0

    #pragma unroll 1
    for (int cb = 0; cb < NCHUNKS; ++cb) {
        __syncthreads();                // gd/ws free (GEMM(cb-1) done)
        prefetch_w(cb);                 // outstanding: R(cb), W(cb)
        cp_wait1();                     // own R(cb) groups retired
        __syncthreads();                // ALL threads' R(cb) complete

        // ---- transform raw x -> duplicated g planes (LDS + MUFU + STS) ----
        #pragma unroll
        for (int k = 0; k < 11; ++k) {
            int idx = tid + k * THREADS;
            if (idx >= STAGE_N) break;
            int c4  = idx / 660;
            int rem = idx - c4 * 660;
            int r   = rem / 66;
            int cc  = rem - r * 66;
            int gy = y0 - 1 + r;
            int gx = x0 - 1 + cc;
            float g1, g2, g3;
            if ((unsigned)gy < (unsigned)NH && (unsigned)gx < (unsigned)NW) {
                float xv = raw[(c4 * 10 + r) * RAWF + cc + 3];
                float t  = fast_tanh(xv);
                float P2 = t * t - B2;
                float P3 = t * P2 - B3 * t;
                g1 = silu_f(t);
                g2 = silu_f(P2);
                g3 = silu_f(P3);
            } else {
                g1 = g2 = g3 = 0.f;
            }
            int sb = (c4 * 3) * GPL + r * 66 + cc;
            gd[sb]           = pack2(g1, g1);
            gd[sb + GPL]     = pack2(g2, g2);
            gd[sb + 2 * GPL] = pack2(g3, g3);
        }
        cp_wait0();                     // own W(cb) groups retired
        __syncthreads();                // all W(cb) + gd visible

        // ---- start next chunk's raw fetch under the GEMM ----
        if (cb + 1 < NCHUNKS) prefetch_raw(cb + 1);   // outstanding: R(cb+1)

        // ---- register-tiled f32x2 GEMM: out-pair weights x dup acts ----
        const ull* wp = ws + og * 4;
        const ull* gb = gd + row * 66 + col0;
        #pragma unroll 2
        for (int ch = 0; ch < NPL; ++ch) {
            #pragma unroll
            for (int ky = 0; ky < 3; ++ky) {
                const ull* gr = gb + ky * 66;
                ulonglong2 A01 = *(const ulonglong2*)(gr);
                ulonglong2 A23 = *(const ulonglong2*)(gr + 2);
                ulonglong2 A45 = *(const ulonglong2*)(gr + 4);
                ulonglong2 B01 = *(const ulonglong2*)(gr + 32);
                ulonglong2 B23 = *(const ulonglong2*)(gr + 34);
                ulonglong2 B45 = *(const ulonglong2*)(gr + 36);
                ull a[6] = {A01.x, A01.y, A23.x, A23.y, A45.x, A45.y};
                ull b[6] = {B01.x, B01.y, B23.x, B23.y, B45.x, B45.y};
                #pragma unroll
                for (int kx = 0; kx < 3; ++kx) {
                    const ull* w = wp + (ky * 3 + kx) * 16;
                    ulonglong2 w01 = *(const ulonglong2*)(w);      // pairs p0,p1
                    ulonglong2 w23 = *(const ulonglong2*)(w + 2);  // pairs p2,p3
                    #pragma unroll
                    for (int j = 0; j < 4; ++j) {
                        fma2(acc[0  + j], w01.x, a[kx + j]);
                        fma2(acc[8  + j], w01.y, a[kx + j]);
                        fma2(acc[16 + j], w23.x, a[kx + j]);
                        fma2(acc[24 + j], w23.y, a[kx + j]);
                        fma2(acc[4  + j], w01.x, b[kx + j]);
                        fma2(acc[12 + j], w01.y, b[kx + j]);
                        fma2(acc[20 + j], w23.x, b[kx + j]);
                        fma2(acc[28 + j], w23.y, b[kx + j]);
                    }
                }
            }
            wp += 9 * 16;
            gb += GPL;
        }
    }

    // ---- epilogue: P0 bias + per-batch gate scale + store ----
    float s = g_scale[n];
    int gy = y0 + row;
    bool top = (gy == 0), bot = (gy == NH - 1);
    #pragma unroll
    for (int p = 0; p < 4; ++p) {
        int o0 = og8 + 2 * p;
        const float* bt0 = g_bias + o0 * 9;
        const float* bt1 = g_bias + (o0 + 1) * 9;
        float bb0 = bt0[0] - (top ? bt0[1] : 0.f) - (bot ? bt0[2] : 0.f);
        float bb1 = bt1[0] - (top ? bt1[1] : 0.f) - (bot ? bt1[2] : 0.f);
        #pragma unroll
        for (int h = 0; h < 2; ++h) {
            int gx0 = x0 + col0 + h * 32;
            float bl0 = bb0, br0 = bb0, bl1 = bb1, br1 = bb1;
            if (gx0 == 0) {
                bl0 += -bt0[3] + (top ? bt0[5] : 0.f) + (bot ? bt0[7] : 0.f);
                bl1 += -bt1[3] + (top ? bt1[5] : 0.f) + (bot ? bt1[7] : 0.f);
            }
            if (gx0 + 3 == NW - 1) {
                br0 += -bt0[4] + (top ? bt0[6] : 0.f) + (bot ? bt0[8] : 0.f);
                br1 += -bt1[4] + (top ? bt1[6] : 0.f) + (bot ? bt1[8] : 0.f);
            }
            float v0[4], v1[4];
            #pragma unroll
            for (int j = 0; j < 4; ++j)
                unpack2(acc[p * 8 + h * 4 + j], v0[j], v1[j]);
            float4 out0, out1;
            out0.x = (v0[0] + bl0) * s;
            out0.y = (v0[1] + bb0) * s;
            out0.z = (v0[2] + bb0) * s;
            out0.w = (v0[3] + br0) * s;
            out1.x = (v1[0] + bl1) * s;
            out1.y = (v1[1] + bb1) * s;
            out1.z = (v1[2] + bb1) * s;
            out1.w = (v1[3] + br1) * s;
            size_t off0 = ((size_t)(n * NC + o0)     * NH + gy) * NW + gx0;
            size_t off1 = ((size_t)(n * NC + o0 + 1) * NH + gy) * NW + gx0;
            *(float4*)(y + off0) = out0;
            *(float4*)(y + off1) = out1;
        }
    }
}

// ---------------- launcher ----------------
extern "C" void kernel_launch(void* const* d_in, const int* in_sizes, int n_in,
                              void* d_out, int out_size) {
    const float* x  = (const float*)d_in[0];
    const float* wg = (const float*)d_in[1];
    const float* pw = (const float*)d_in[2];
    const float* bw = (const float*)d_in[3];
    float* out = (float*)d_out;

    cudaFuncSetAttribute(k_moe_conv, cudaFuncAttributeMaxDynamicSharedMemorySize, SMEM_BYTES);

    k_gate<<<NB * NC, 256>>>(x, wg, out + (out_size - 1));    // launch 0
    k_wprep<<<55, 256>>>(pw);                                  // launch 1
    k_spacer<<<1, 32>>>();                                     // launch 2 (aligns ncu)
    dim3 grid(NW / TW, NH / TH, NB);
    k_moe_conv<<<grid, THREADS, SMEM_BYTES>>>(x, bw, out);     // launch 3 <- profiled
}